// round 15
// baseline (speedup 1.0000x reference)
#include <cuda_runtime.h>
#include <math.h>

#define BB 2
#define KK 4096
#define DD 192
#define D2 96            // float2 channels
#define H1 96
#define W1 320
#define H2 48
#define W2 160
#define H3 24
#define W3 80
#define H4 12
#define W4 40
#define NQ (BB * KK)
#define QT 8

// Scratch (allocation-free __device__ globals, 16B aligned)
__device__ __align__(16) float g_m1[(size_t)BB * H1 * W1 * DD];
__device__ __align__(16) float g_c1[(size_t)BB * H1 * W1 * 64];
__device__ __align__(16) float g_m2[(size_t)BB * H2 * W2 * DD];
__device__ __align__(16) float g_m3[(size_t)BB * H3 * W3 * DD];
__device__ __align__(16) float g_m4[(size_t)BB * H4 * W4 * DD];
__device__ __align__(16) float g_phiW[24 * DD];               // phi(fixed)@W2 + w_loc_b
__device__ __align__(16) float g_phiLW2[(size_t)NQ * 8 * DD]; // phi(learned)@W2 + w_loc_b
__device__ __align__(16) float g_lxy[(size_t)NQ * 16];        // interleaved (lx,ly)

#define TWO_PI 6.283185307179586f

// ---------------- scalarized float2 helpers (no pack/unpack MOVs) ----------------
__device__ __forceinline__ float2 f2fma(float2 a, float2 b, float2 c) {
    return make_float2(fmaf(a.x, b.x, c.x), fmaf(a.y, b.y, c.y));
}
__device__ __forceinline__ float2 f2mul(float2 a, float2 b) {
    return make_float2(a.x * b.x, a.y * b.y);
}
__device__ __forceinline__ float2 f2add(float2 a, float2 b) {
    return make_float2(a.x + b.x, a.y + b.y);
}
__device__ __forceinline__ float2 bc2(float s) { return make_float2(s, s); }

__device__ __forceinline__ float gelu1(float v) {
    return 0.5f * v * (1.f + erff(v * 0.7071067811865476f));
}
__device__ __forceinline__ float2 gelu2(float2 v) {
    return make_float2(gelu1(v.x), gelu1(v.y));
}

// ---------------------------------------------------------------------------
// Precompute: out[b, p, d] = sum_c feat[b, c, p] * Wm[c, d]   (channel-last)
// ---------------------------------------------------------------------------
template <int CIN, int LVL>
__global__ __launch_bounds__(DD) void proj_map_kernel(
    const float* __restrict__ feat, const float* __restrict__ Wm, int npix)
{
    constexpr int TX = 8;
    __shared__ float sf[CIN * TX];
    float* outmap = (LVL == 1) ? g_m1 : (LVL == 2) ? g_m2 : g_m4;

    const int b = blockIdx.y;
    const int p0 = blockIdx.x * TX;
    const float* fb = feat + (size_t)b * CIN * npix + p0;

    for (int i = threadIdx.x; i < CIN * TX; i += DD) {
        int c = i >> 3, p = i & 7;
        sf[i] = fb[(size_t)c * npix + p];
    }
    __syncthreads();

    if (LVL == 1) {
        for (int i = threadIdx.x; i < 64 * TX; i += DD) {
            int p = i >> 6, c = i & 63;
            g_c1[((size_t)b * npix + p0 + p) * 64 + c] = sf[c * TX + p];
        }
    }

    const int d = threadIdx.x;
    float acc[TX];
#pragma unroll
    for (int p = 0; p < TX; p++) acc[p] = 0.f;

    for (int c = 0; c < CIN; c++) {
        float w = Wm[c * DD + d];
#pragma unroll
        for (int p = 0; p < TX; p++) acc[p] = fmaf(sf[c * TX + p], w, acc[p]);
    }

    float* ob = outmap + ((size_t)b * npix + p0) * DD + d;
#pragma unroll
    for (int p = 0; p < TX; p++) ob[p * DD] = acc[p];
}

// Channel-last transpose for l3
__global__ __launch_bounds__(256) void l3_transpose_kernel(const float* __restrict__ feat)
{
    __shared__ float s[32][33];
    const int npix = H3 * W3;
    const int b = blockIdx.y;
    const int p0 = blockIdx.x * 32;
    const int d0 = blockIdx.z * 32;

#pragma unroll
    for (int k = 0; k < 4; k++) {
        int i = threadIdx.x + k * 256;
        int d = i >> 5, p = i & 31;
        s[p][d] = feat[((size_t)b * DD + d0 + d) * npix + p0 + p];
    }
    __syncthreads();
#pragma unroll
    for (int k = 0; k < 4; k++) {
        int i = threadIdx.x + k * 256;
        int p = i >> 5, d = i & 31;
        g_m3[((size_t)b * npix + p0 + p) * DD + d0 + d] = s[p][d];
    }
}

// g_phiW = phi(fixed_off) @ w_loc_w[64:80] + w_loc_b
__global__ __launch_bounds__(DD) void init_tables_kernel(
    const float* __restrict__ w_loc_w, const float* __restrict__ w_loc_b)
{
    const int t = blockIdx.x;
    const int d = threadIdx.x;
    int idx = (t < 12) ? t : t + 1;
    float dx = (float)(idx % 5 - 2), dy = (float)(idx / 5 - 2);
    float a = w_loc_b[d];
#pragma unroll
    for (int j = 0; j < 16; j++) {
        float c = (j < 8) ? dx : dy;
        float ang = c * TWO_PI * (float)(1 << (j & 3));
        float v = ((j >> 2) & 1) ? cosf(ang) : sinf(ang);
        a = fmaf(v, w_loc_w[(64 + j) * DD + d], a);
    }
    g_phiW[t * DD + d] = a;
}

// ---------------------------------------------------------------------------
// Seed + learned-offset kernel
// ---------------------------------------------------------------------------
__global__ __launch_bounds__(DD) void seed_off_kernel(
    const float* __restrict__ coords,
    const float* __restrict__ w_off_w, const float* __restrict__ w_off_b,
    const float* __restrict__ w_loc_w, const float* __restrict__ w_loc_b,
    const float* __restrict__ w_q_w,   const float* __restrict__ w_q_b,
    float* __restrict__ out_seed)
{
    __shared__ float s_f[QT][96];
    __shared__ float s_wo[64 * 16];
    __shared__ float s_w2[16 * DD];
    __shared__ float s_lxy[QT][16];
    __shared__ float s_phi[QT * 128];

    const int tid = threadIdx.x;
    const int q0 = blockIdx.x * QT;

    for (int i = tid; i < 64 * 16; i += DD) s_wo[i] = w_off_w[i];
    for (int i = tid; i < 16 * DD; i += DD) s_w2[i] = w_loc_w[64 * DD + i];

    {
        const int sub = tid >> 6, c = tid & 63;
        for (int q = sub; q < QT; q += 3) {
            const int qi = q0 + q;
            const int b = qi >> 12;
            const float x = coords[2 * qi], y = coords[2 * qi + 1];
            float xs = x * 0.25f, ys = y * 0.25f;
            float x0f = floorf(xs), y0f = floorf(ys);
            float wx1 = xs - x0f, wy1 = ys - y0f;
            float wx0 = 1.f - wx1, wy0 = 1.f - wy1;
            int x0 = (int)x0f, y0 = (int)y0f, x1 = x0 + 1, y1 = y0 + 1;
            bool vx0 = (unsigned)x0 < (unsigned)W1, vx1 = (unsigned)x1 < (unsigned)W1;
            const float* cb = g_c1 + (size_t)b * (H1 * W1) * 64 + c;
            float acc = 0.f;
            if ((unsigned)y0 < (unsigned)H1) {
                if (vx0) acc = fmaf(wx0 * wy0, cb[(size_t)(y0 * W1 + x0) * 64], acc);
                if (vx1) acc = fmaf(wx1 * wy0, cb[(size_t)(y0 * W1 + x1) * 64], acc);
            }
            if ((unsigned)y1 < (unsigned)H1) {
                if (vx0) acc = fmaf(wx0 * wy1, cb[(size_t)(y1 * W1 + x0) * 64], acc);
                if (vx1) acc = fmaf(wx1 * wy1, cb[(size_t)(y1 * W1 + x1) * 64], acc);
            }
            s_f[q][c] = acc;
        }
    }
    for (int i = tid; i < QT * 32; i += DD) {
        int q = i >> 5, j = i & 31;
        const int qi = q0 + q;
        float cv = (j < 16) ? coords[2 * qi] * (1.f / 1280.f)
                            : coords[2 * qi + 1] * (1.f / 384.f);
        float ang = cv * TWO_PI * (float)(1 << (j & 7));
        s_f[q][64 + j] = ((j >> 3) & 1) ? cosf(ang) : sinf(ang);
    }
    __syncthreads();

    if (tid < QT * 16) {
        int q = tid >> 4, j = tid & 15;
        float a = w_off_b[j];
#pragma unroll 8
        for (int c = 0; c < 64; c++) a = fmaf(s_f[q][c], s_wo[c * 16 + j], a);
        float v = 6.f * tanhf(a);
        int slot = (j & 1) ? 8 + (j >> 1) : (j >> 1);
        s_lxy[q][slot] = v;
        g_lxy[(size_t)(q0 + q) * 16 + (j >> 1) * 2 + (j & 1)] = v;
    }
    __syncthreads();

    for (int i = tid; i < QT * 128; i += DD) {
        int q = i >> 7, r = i & 127;
        int t = r >> 4, j = r & 15;
        float c = (j < 8) ? s_lxy[q][t] : s_lxy[q][8 + t];
        float ang = c * TWO_PI * (float)(1 << (j & 3));
        s_phi[i] = ((j >> 2) & 1) ? cosf(ang) : sinf(ang);
    }

    {
        const int d = tid;
        float acc[QT];
        float bq = w_q_b[d];
#pragma unroll
        for (int q = 0; q < QT; q++) acc[q] = bq;
        for (int c = 0; c < 96; c++) {
            float w = w_q_w[c * DD + d];
#pragma unroll
            for (int q = 0; q < QT; q++) acc[q] = fmaf(s_f[q][c], w, acc[q]);
        }
#pragma unroll
        for (int q = 0; q < QT; q++)
            out_seed[(size_t)(q0 + q) * DD + d] = acc[q];
    }
    __syncthreads();

    {
        const int d = tid;
        const float wlbd = w_loc_b[d];
        for (int qt = 0; qt < QT * 8; qt++) {
            int q = qt >> 3, t = qt & 7;
            float a = wlbd;
            const float* ph = &s_phi[q * 128 + t * 16];
#pragma unroll
            for (int j = 0; j < 16; j++) a = fmaf(ph[j], s_w2[j * DD + d], a);
            __stcs(&g_phiLW2[((size_t)(q0 + q) * 8 + t) * DD + d], a);
        }
    }
}

// ---------------------------------------------------------------------------
// float2 bilinear sample (arbitrary position) with warp-uniform interior path
// ---------------------------------------------------------------------------
template <int H, int W>
__device__ __forceinline__ float2 sample2(const float2* __restrict__ md,
                                          float x, float y)
{
    float x0f = floorf(x), y0f = floorf(y);
    float wx1 = x - x0f, wy1 = y - y0f;
    float wx0 = 1.f - wx1, wy0 = 1.f - wy1;
    int x0 = (int)x0f, y0 = (int)y0f;

    if (x0 >= 0 && y0 >= 0 && x0 + 1 < W && y0 + 1 < H) {
        const float2* r0 = md + (y0 * W + x0) * D2;
        float2 p00 = r0[0],        p01 = r0[D2];
        float2 p10 = r0[W * D2],   p11 = r0[W * D2 + D2];
        float2 h0 = f2fma(bc2(wx1), p01, f2mul(bc2(wx0), p00));
        float2 h1 = f2fma(bc2(wx1), p11, f2mul(bc2(wx0), p10));
        return f2fma(bc2(wy1), h1, f2mul(bc2(wy0), h0));
    }

    int x1 = x0 + 1, y1 = y0 + 1;
    bool vx0 = (unsigned)x0 < (unsigned)W;
    bool vx1 = (unsigned)x1 < (unsigned)W;
    bool vy0 = (unsigned)y0 < (unsigned)H;
    bool vy1 = (unsigned)y1 < (unsigned)H;

    float2 z = make_float2(0.f, 0.f);
    float2 p00 = (vy0 && vx0) ? md[(y0 * W + x0) * D2] : z;
    float2 p01 = (vy0 && vx1) ? md[(y0 * W + x1) * D2] : z;
    float2 p10 = (vy1 && vx0) ? md[(y1 * W + x0) * D2] : z;
    float2 p11 = (vy1 && vx1) ? md[(y1 * W + x1) * D2] : z;

    float2 h0 = f2fma(bc2(wx1), p01, f2mul(bc2(wx0), p00));
    float2 h1 = f2fma(bc2(wx1), p11, f2mul(bc2(wx0), p10));
    return f2fma(bc2(wy1), h1, f2mul(bc2(wy0), h0));
}

// Patch-shared float2 bilinear; warp-uniform interior fast path with
// immediate-offset loads and a single row-pointer increment.
template <int H, int W, int R, typename F>
__device__ __forceinline__ void patch_sample2(const float2* __restrict__ md,
                                              float xs, float ys, F&& emit)
{
    constexpr int PC = 2 * R + 2;
    float xf = floorf(xs), yf = floorf(ys);
    float2 bwx1 = bc2(xs - xf), bwx0 = bc2(1.f - (xs - xf));
    float2 bwy1 = bc2(ys - yf), bwy0 = bc2(1.f - (ys - yf));
    int bx0 = (int)xf - R, by0 = (int)yf - R;

    float2 hprev[PC - 1];

    if (bx0 >= 0 && by0 >= 0 && bx0 + PC <= W && by0 + PC <= H) {
        // interior: no bounds checks, compile-time column offsets
        const float2* rowp = md + (by0 * W + bx0) * D2;
#pragma unroll
        for (int r = 0; r < PC; r++) {
            float2 p[PC];
#pragma unroll
            for (int c = 0; c < PC; c++) p[c] = rowp[c * D2];
            rowp += W * D2;
            float2 hcur[PC - 1];
#pragma unroll
            for (int c = 0; c < PC - 1; c++)
                hcur[c] = f2fma(bwx1, p[c + 1], f2mul(bwx0, p[c]));
            if (r > 0) {
#pragma unroll
                for (int c = 0; c < PC - 1; c++)
                    emit(r - 1, c, f2fma(bwy1, hcur[c], f2mul(bwy0, hprev[c])));
            }
#pragma unroll
            for (int c = 0; c < PC - 1; c++) hprev[c] = hcur[c];
        }
        return;
    }

    // boundary: per-corner clamping (rare, warp-uniform)
    const float2 z = make_float2(0.f, 0.f);
    for (int r = 0; r < PC; r++) {
        int yy = by0 + r;
        bool yok = (unsigned)yy < (unsigned)H;
        float2 p[PC];
#pragma unroll
        for (int c = 0; c < PC; c++) {
            int xx = bx0 + c;
            bool ok = yok && ((unsigned)xx < (unsigned)W);
            p[c] = ok ? md[(yy * W + xx) * D2] : z;
        }
        float2 hcur[PC - 1];
#pragma unroll
        for (int c = 0; c < PC - 1; c++)
            hcur[c] = f2fma(bwx1, p[c + 1], f2mul(bwx0, p[c]));
        if (r > 0) {
#pragma unroll
            for (int c = 0; c < PC - 1; c++)
                emit(r - 1, c, f2fma(bwy1, hcur[c], f2mul(bwy0, hprev[c])));
        }
#pragma unroll
        for (int c = 0; c < PC - 1; c++) hprev[c] = hcur[c];
    }
}

// ---------------------------------------------------------------------------
// Gather kernel: 192 threads = 2 independent 96-thread query groups.
// Per-level loops; no smem; (192,4) bound; interior fast paths.
// ---------------------------------------------------------------------------
__global__ __launch_bounds__(DD, 4) void gather_kernel(
    const float* __restrict__ coords,
    const float* __restrict__ proj_l2_b, const float* __restrict__ proj_l4_b,
    const float* __restrict__ e_l1, const float* __restrict__ e_l2,
    const float* __restrict__ e_l3, const float* __restrict__ e_l4,
    const float* __restrict__ rpe,
    float* __restrict__ out_tokens)
{
    const int tid = threadIdx.x;
    const int q0 = blockIdx.x * QT;
    const int g = tid / D2;
    const int c = tid % D2;

    const float2* crd = (const float2*)coords;
    const float2* rp = (const float2*)rpe;
    const float2* pwt = (const float2*)g_phiW;

    // ---- Loop 1: l1 fixed (24) + learned (8) tokens ----
    {
        const float2 e1 = ((const float2*)e_l1)[c];
        const float2* lxy2 = (const float2*)g_lxy;
        const float2* phiLW2 = (const float2*)g_phiLW2;
        for (int qq = g; qq < QT; qq += 2) {
            const int qi = q0 + qq;
            const int b = qi >> 12;
            const float2 xy = __ldg(&crd[qi]);
            const float xc = xy.x * 0.25f, yc = xy.y * 0.25f;
            float2* tb = (float2*)out_tokens + (size_t)qi * 91 * D2 + c;
            const float2* m1b = (const float2*)g_m1 + (size_t)b * (H1 * W1) * D2 + c;

            patch_sample2<H1, W1, 2>(m1b, xc, yc,
                [&](int ty, int tx, float2 v) {
                    int idx = ty * 5 + tx;
                    if (idx == 12) return;
                    int t = (idx < 12) ? idx : idx - 1;
                    v = f2add(v, __ldg(&pwt[t * D2 + c]));
                    __stcs(&tb[t * D2], f2add(gelu2(v), e1));
                });

            for (int t = 0; t < 8; t++) {
                float2 off = __ldg(&lxy2[(size_t)qi * 8 + t]);
                float2 v = sample2<H1, W1>(m1b, xc + off.x, yc + off.y);
                float2 pw = __ldcs(&phiLW2[((size_t)qi * 8 + t) * D2 + c]);
                v = f2add(v, pw);
                __stcs(&tb[(24 + t) * D2], f2add(gelu2(v), e1));
            }
        }
    }

    // ---- Loop 2: l2 tokens (25) ----
    {
        const float2 b2e = f2add(((const float2*)proj_l2_b)[c], ((const float2*)e_l2)[c]);
        for (int qq = g; qq < QT; qq += 2) {
            const int qi = q0 + qq;
            const int b = qi >> 12;
            const float2 xy = __ldg(&crd[qi]);
            float2* tb = (float2*)out_tokens + (size_t)qi * 91 * D2 + c;
            const float2* m2b = (const float2*)g_m2 + (size_t)b * (H2 * W2) * D2 + c;
            patch_sample2<H2, W2, 2>(m2b, xy.x * 0.125f, xy.y * 0.125f,
                [&](int ty, int tx, float2 v) {
                    int t = ty * 5 + tx;
                    __stcs(&tb[(32 + t) * D2],
                           f2add(f2add(v, b2e), __ldg(&rp[t * D2 + c])));
                });
        }
    }

    // ---- Loop 3: l3 tokens (25) ----
    {
        const float2 e3 = ((const float2*)e_l3)[c];
        for (int qq = g; qq < QT; qq += 2) {
            const int qi = q0 + qq;
            const int b = qi >> 12;
            const float2 xy = __ldg(&crd[qi]);
            float2* tb = (float2*)out_tokens + (size_t)qi * 91 * D2 + c;
            const float2* m3b = (const float2*)g_m3 + (size_t)b * (H3 * W3) * D2 + c;
            patch_sample2<H3, W3, 2>(m3b, xy.x * 0.0625f, xy.y * 0.0625f,
                [&](int ty, int tx, float2 v) {
                    int t = ty * 5 + tx;
                    __stcs(&tb[(57 + t) * D2],
                           f2add(f2add(v, e3), __ldg(&rp[t * D2 + c])));
                });
        }
    }

    // ---- Loop 4: l4 tokens (9) ----
    {
        const float2 b4e = f2add(((const float2*)proj_l4_b)[c], ((const float2*)e_l4)[c]);
        for (int qq = g; qq < QT; qq += 2) {
            const int qi = q0 + qq;
            const int b = qi >> 12;
            const float2 xy = __ldg(&crd[qi]);
            float2* tb = (float2*)out_tokens + (size_t)qi * 91 * D2 + c;
            const float2* m4b = (const float2*)g_m4 + (size_t)b * (H4 * W4) * D2 + c;
            patch_sample2<H4, W4, 1>(m4b, xy.x * 0.03125f, xy.y * 0.03125f,
                [&](int ty, int tx, float2 v) {
                    int t = ty * 3 + tx;
                    int ridx = 6 + (t / 3) * 5 + (t % 3);
                    __stcs(&tb[(82 + t) * D2],
                           f2add(f2add(v, b4e), __ldg(&rp[ridx * D2 + c])));
                });
        }
    }
}

// ---------------------------------------------------------------------------
extern "C" void kernel_launch(void* const* d_in, const int* in_sizes, int n_in,
                              void* d_out, int out_size)
{
    const float* feat_l1   = (const float*)d_in[0];
    const float* feat_l2   = (const float*)d_in[1];
    const float* feat_l3   = (const float*)d_in[2];
    const float* feat_l4   = (const float*)d_in[3];
    const float* coords    = (const float*)d_in[4];
    const float* proj_l2_w = (const float*)d_in[5];
    const float* proj_l2_b = (const float*)d_in[6];
    const float* proj_l4_w = (const float*)d_in[7];
    const float* proj_l4_b = (const float*)d_in[8];
    const float* w_off_w   = (const float*)d_in[9];
    const float* w_off_b   = (const float*)d_in[10];
    const float* w_loc_w   = (const float*)d_in[11];
    const float* w_loc_b   = (const float*)d_in[12];
    const float* w_q_w     = (const float*)d_in[13];
    const float* w_q_b     = (const float*)d_in[14];
    const float* e_l1      = (const float*)d_in[15];
    const float* e_l2      = (const float*)d_in[16];
    const float* e_l3      = (const float*)d_in[17];
    const float* e_l4      = (const float*)d_in[18];
    const float* rpe       = (const float*)d_in[19];

    float* out = (float*)d_out;
    float* out_tokens = out;
    float* out_seed = out + (size_t)NQ * 91 * DD;

    proj_map_kernel<64, 1><<<dim3(H1 * W1 / 8, BB), DD>>>(feat_l1, w_loc_w, H1 * W1);
    proj_map_kernel<128, 2><<<dim3(H2 * W2 / 8, BB), DD>>>(feat_l2, proj_l2_w, H2 * W2);
    proj_map_kernel<384, 4><<<dim3(H4 * W4 / 8, BB), DD>>>(feat_l4, proj_l4_w, H4 * W4);
    l3_transpose_kernel<<<dim3(H3 * W3 / 32, BB, 6), 256>>>(feat_l3);
    init_tables_kernel<<<24, DD>>>(w_loc_w, w_loc_b);

    seed_off_kernel<<<NQ / QT, DD>>>(coords, w_off_w, w_off_b, w_loc_w, w_loc_b,
                                     w_q_w, w_q_b, out_seed);

    gather_kernel<<<NQ / QT, DD>>>(coords, proj_l2_b, proj_l4_b,
                                   e_l1, e_l2, e_l3, e_l4, rpe, out_tokens);
}

// round 16
// speedup vs baseline: 1.0376x; 1.0376x over previous
#include <cuda_runtime.h>
#include <math.h>

#define BB 2
#define KK 4096
#define DD 192
#define D2 96            // float2 channels
#define H1 96
#define W1 320
#define H2 48
#define W2 160
#define H3 24
#define W3 80
#define H4 12
#define W4 40
#define NQ (BB * KK)
#define QT 8

// Scratch (allocation-free __device__ globals, 16B aligned)
__device__ __align__(16) float g_m1[(size_t)BB * H1 * W1 * DD];
__device__ __align__(16) float g_c1[(size_t)BB * H1 * W1 * 64];
__device__ __align__(16) float g_m2[(size_t)BB * H2 * W2 * DD];
__device__ __align__(16) float g_m3[(size_t)BB * H3 * W3 * DD];
__device__ __align__(16) float g_m4[(size_t)BB * H4 * W4 * DD];
__device__ __align__(16) float g_phiW[24 * DD];               // phi(fixed)@W2 + w_loc_b
__device__ __align__(16) float g_phiLW2[(size_t)NQ * 8 * DD]; // phi(learned)@W2 + w_loc_b
__device__ __align__(16) float g_lxy[(size_t)NQ * 16];        // interleaved (lx,ly)

#define TWO_PI 6.283185307179586f

// ---------------- scalarized float2 helpers ----------------
__device__ __forceinline__ float2 f2fma(float2 a, float2 b, float2 c) {
    return make_float2(fmaf(a.x, b.x, c.x), fmaf(a.y, b.y, c.y));
}
__device__ __forceinline__ float2 f2mul(float2 a, float2 b) {
    return make_float2(a.x * b.x, a.y * b.y);
}
__device__ __forceinline__ float2 f2add(float2 a, float2 b) {
    return make_float2(a.x + b.x, a.y + b.y);
}
__device__ __forceinline__ float2 bc2(float s) { return make_float2(s, s); }

// Fast GELU: tanh approximation with single-MUFU tanh.approx.f32.
// |gelu_tanh - gelu_exact| <= ~3e-4 abs (peak at |v|~2.2); inputs here have
// std ~0.16 so typical error is ~1e-5. HW tanh.approx adds ~2^-11 rel.
__device__ __forceinline__ float gelu1(float v) {
    float u = 0.7978845608028654f * fmaf(0.044715f * v, v * v, v);
    float t;
    asm("tanh.approx.f32 %0, %1;" : "=f"(t) : "f"(u));
    return 0.5f * v * (1.f + t);
}
__device__ __forceinline__ float2 gelu2(float2 v) {
    return make_float2(gelu1(v.x), gelu1(v.y));
}

// ---------------------------------------------------------------------------
// Precompute: out[b, p, d] = sum_c feat[b, c, p] * Wm[c, d]   (channel-last)
// ---------------------------------------------------------------------------
template <int CIN, int LVL>
__global__ __launch_bounds__(DD) void proj_map_kernel(
    const float* __restrict__ feat, const float* __restrict__ Wm, int npix)
{
    constexpr int TX = 8;
    __shared__ float sf[CIN * TX];
    float* outmap = (LVL == 1) ? g_m1 : (LVL == 2) ? g_m2 : g_m4;

    const int b = blockIdx.y;
    const int p0 = blockIdx.x * TX;
    const float* fb = feat + (size_t)b * CIN * npix + p0;

    for (int i = threadIdx.x; i < CIN * TX; i += DD) {
        int c = i >> 3, p = i & 7;
        sf[i] = fb[(size_t)c * npix + p];
    }
    __syncthreads();

    if (LVL == 1) {
        for (int i = threadIdx.x; i < 64 * TX; i += DD) {
            int p = i >> 6, c = i & 63;
            g_c1[((size_t)b * npix + p0 + p) * 64 + c] = sf[c * TX + p];
        }
    }

    const int d = threadIdx.x;
    float acc[TX];
#pragma unroll
    for (int p = 0; p < TX; p++) acc[p] = 0.f;

    for (int c = 0; c < CIN; c++) {
        float w = Wm[c * DD + d];
#pragma unroll
        for (int p = 0; p < TX; p++) acc[p] = fmaf(sf[c * TX + p], w, acc[p]);
    }

    float* ob = outmap + ((size_t)b * npix + p0) * DD + d;
#pragma unroll
    for (int p = 0; p < TX; p++) ob[p * DD] = acc[p];
}

// Channel-last transpose for l3
__global__ __launch_bounds__(256) void l3_transpose_kernel(const float* __restrict__ feat)
{
    __shared__ float s[32][33];
    const int npix = H3 * W3;
    const int b = blockIdx.y;
    const int p0 = blockIdx.x * 32;
    const int d0 = blockIdx.z * 32;

#pragma unroll
    for (int k = 0; k < 4; k++) {
        int i = threadIdx.x + k * 256;
        int d = i >> 5, p = i & 31;
        s[p][d] = feat[((size_t)b * DD + d0 + d) * npix + p0 + p];
    }
    __syncthreads();
#pragma unroll
    for (int k = 0; k < 4; k++) {
        int i = threadIdx.x + k * 256;
        int p = i >> 5, d = i & 31;
        g_m3[((size_t)b * npix + p0 + p) * DD + d0 + d] = s[p][d];
    }
}

// g_phiW = phi(fixed_off) @ w_loc_w[64:80] + w_loc_b
__global__ __launch_bounds__(DD) void init_tables_kernel(
    const float* __restrict__ w_loc_w, const float* __restrict__ w_loc_b)
{
    const int t = blockIdx.x;
    const int d = threadIdx.x;
    int idx = (t < 12) ? t : t + 1;
    float dx = (float)(idx % 5 - 2), dy = (float)(idx / 5 - 2);
    float a = w_loc_b[d];
#pragma unroll
    for (int j = 0; j < 16; j++) {
        float c = (j < 8) ? dx : dy;
        float ang = c * TWO_PI * (float)(1 << (j & 3));
        float v = ((j >> 2) & 1) ? cosf(ang) : sinf(ang);
        a = fmaf(v, w_loc_w[(64 + j) * DD + d], a);
    }
    g_phiW[t * DD + d] = a;
}

// ---------------------------------------------------------------------------
// Seed + learned-offset kernel
// ---------------------------------------------------------------------------
__global__ __launch_bounds__(DD) void seed_off_kernel(
    const float* __restrict__ coords,
    const float* __restrict__ w_off_w, const float* __restrict__ w_off_b,
    const float* __restrict__ w_loc_w, const float* __restrict__ w_loc_b,
    const float* __restrict__ w_q_w,   const float* __restrict__ w_q_b,
    float* __restrict__ out_seed)
{
    __shared__ float s_f[QT][96];
    __shared__ float s_wo[64 * 16];
    __shared__ float s_w2[16 * DD];
    __shared__ float s_lxy[QT][16];
    __shared__ float s_phi[QT * 128];

    const int tid = threadIdx.x;
    const int q0 = blockIdx.x * QT;

    for (int i = tid; i < 64 * 16; i += DD) s_wo[i] = w_off_w[i];
    for (int i = tid; i < 16 * DD; i += DD) s_w2[i] = w_loc_w[64 * DD + i];

    {
        const int sub = tid >> 6, c = tid & 63;
        for (int q = sub; q < QT; q += 3) {
            const int qi = q0 + q;
            const int b = qi >> 12;
            const float x = coords[2 * qi], y = coords[2 * qi + 1];
            float xs = x * 0.25f, ys = y * 0.25f;
            float x0f = floorf(xs), y0f = floorf(ys);
            float wx1 = xs - x0f, wy1 = ys - y0f;
            float wx0 = 1.f - wx1, wy0 = 1.f - wy1;
            int x0 = (int)x0f, y0 = (int)y0f, x1 = x0 + 1, y1 = y0 + 1;
            bool vx0 = (unsigned)x0 < (unsigned)W1, vx1 = (unsigned)x1 < (unsigned)W1;
            const float* cb = g_c1 + (size_t)b * (H1 * W1) * 64 + c;
            float acc = 0.f;
            if ((unsigned)y0 < (unsigned)H1) {
                if (vx0) acc = fmaf(wx0 * wy0, cb[(size_t)(y0 * W1 + x0) * 64], acc);
                if (vx1) acc = fmaf(wx1 * wy0, cb[(size_t)(y0 * W1 + x1) * 64], acc);
            }
            if ((unsigned)y1 < (unsigned)H1) {
                if (vx0) acc = fmaf(wx0 * wy1, cb[(size_t)(y1 * W1 + x0) * 64], acc);
                if (vx1) acc = fmaf(wx1 * wy1, cb[(size_t)(y1 * W1 + x1) * 64], acc);
            }
            s_f[q][c] = acc;
        }
    }
    for (int i = tid; i < QT * 32; i += DD) {
        int q = i >> 5, j = i & 31;
        const int qi = q0 + q;
        float cv = (j < 16) ? coords[2 * qi] * (1.f / 1280.f)
                            : coords[2 * qi + 1] * (1.f / 384.f);
        float ang = cv * TWO_PI * (float)(1 << (j & 7));
        s_f[q][64 + j] = ((j >> 3) & 1) ? cosf(ang) : sinf(ang);
    }
    __syncthreads();

    if (tid < QT * 16) {
        int q = tid >> 4, j = tid & 15;
        float a = w_off_b[j];
#pragma unroll 8
        for (int c = 0; c < 64; c++) a = fmaf(s_f[q][c], s_wo[c * 16 + j], a);
        float v = 6.f * tanhf(a);
        int slot = (j & 1) ? 8 + (j >> 1) : (j >> 1);
        s_lxy[q][slot] = v;
        g_lxy[(size_t)(q0 + q) * 16 + (j >> 1) * 2 + (j & 1)] = v;
    }
    __syncthreads();

    for (int i = tid; i < QT * 128; i += DD) {
        int q = i >> 7, r = i & 127;
        int t = r >> 4, j = r & 15;
        float c = (j < 8) ? s_lxy[q][t] : s_lxy[q][8 + t];
        float ang = c * TWO_PI * (float)(1 << (j & 3));
        s_phi[i] = ((j >> 2) & 1) ? cosf(ang) : sinf(ang);
    }

    {
        const int d = tid;
        float acc[QT];
        float bq = w_q_b[d];
#pragma unroll
        for (int q = 0; q < QT; q++) acc[q] = bq;
        for (int c = 0; c < 96; c++) {
            float w = w_q_w[c * DD + d];
#pragma unroll
            for (int q = 0; q < QT; q++) acc[q] = fmaf(s_f[q][c], w, acc[q]);
        }
#pragma unroll
        for (int q = 0; q < QT; q++)
            out_seed[(size_t)(q0 + q) * DD + d] = acc[q];
    }
    __syncthreads();

    {
        const int d = tid;
        const float wlbd = w_loc_b[d];
        for (int qt = 0; qt < QT * 8; qt++) {
            int q = qt >> 3, t = qt & 7;
            float a = wlbd;
            const float* ph = &s_phi[q * 128 + t * 16];
#pragma unroll
            for (int j = 0; j < 16; j++) a = fmaf(ph[j], s_w2[j * DD + d], a);
            __stcs(&g_phiLW2[((size_t)(q0 + q) * 8 + t) * DD + d], a);
        }
    }
}

// ---------------------------------------------------------------------------
// float2 bilinear sample (arbitrary position) with warp-uniform interior path
// ---------------------------------------------------------------------------
template <int H, int W>
__device__ __forceinline__ float2 sample2(const float2* __restrict__ md,
                                          float x, float y)
{
    float x0f = floorf(x), y0f = floorf(y);
    float wx1 = x - x0f, wy1 = y - y0f;
    float wx0 = 1.f - wx1, wy0 = 1.f - wy1;
    int x0 = (int)x0f, y0 = (int)y0f;

    if (x0 >= 0 && y0 >= 0 && x0 + 1 < W && y0 + 1 < H) {
        const float2* r0 = md + (y0 * W + x0) * D2;
        float2 p00 = r0[0],        p01 = r0[D2];
        float2 p10 = r0[W * D2],   p11 = r0[W * D2 + D2];
        float2 h0 = f2fma(bc2(wx1), p01, f2mul(bc2(wx0), p00));
        float2 h1 = f2fma(bc2(wx1), p11, f2mul(bc2(wx0), p10));
        return f2fma(bc2(wy1), h1, f2mul(bc2(wy0), h0));
    }

    int x1 = x0 + 1, y1 = y0 + 1;
    bool vx0 = (unsigned)x0 < (unsigned)W;
    bool vx1 = (unsigned)x1 < (unsigned)W;
    bool vy0 = (unsigned)y0 < (unsigned)H;
    bool vy1 = (unsigned)y1 < (unsigned)H;

    float2 z = make_float2(0.f, 0.f);
    float2 p00 = (vy0 && vx0) ? md[(y0 * W + x0) * D2] : z;
    float2 p01 = (vy0 && vx1) ? md[(y0 * W + x1) * D2] : z;
    float2 p10 = (vy1 && vx0) ? md[(y1 * W + x0) * D2] : z;
    float2 p11 = (vy1 && vx1) ? md[(y1 * W + x1) * D2] : z;

    float2 h0 = f2fma(bc2(wx1), p01, f2mul(bc2(wx0), p00));
    float2 h1 = f2fma(bc2(wx1), p11, f2mul(bc2(wx0), p10));
    return f2fma(bc2(wy1), h1, f2mul(bc2(wy0), h0));
}

// Patch-shared float2 bilinear; warp-uniform interior fast path with
// immediate-offset loads and a single row-pointer increment.
template <int H, int W, int R, typename F>
__device__ __forceinline__ void patch_sample2(const float2* __restrict__ md,
                                              float xs, float ys, F&& emit)
{
    constexpr int PC = 2 * R + 2;
    float xf = floorf(xs), yf = floorf(ys);
    float2 bwx1 = bc2(xs - xf), bwx0 = bc2(1.f - (xs - xf));
    float2 bwy1 = bc2(ys - yf), bwy0 = bc2(1.f - (ys - yf));
    int bx0 = (int)xf - R, by0 = (int)yf - R;

    float2 hprev[PC - 1];

    if (bx0 >= 0 && by0 >= 0 && bx0 + PC <= W && by0 + PC <= H) {
        const float2* rowp = md + (by0 * W + bx0) * D2;
#pragma unroll
        for (int r = 0; r < PC; r++) {
            float2 p[PC];
#pragma unroll
            for (int c = 0; c < PC; c++) p[c] = rowp[c * D2];
            rowp += W * D2;
            float2 hcur[PC - 1];
#pragma unroll
            for (int c = 0; c < PC - 1; c++)
                hcur[c] = f2fma(bwx1, p[c + 1], f2mul(bwx0, p[c]));
            if (r > 0) {
#pragma unroll
                for (int c = 0; c < PC - 1; c++)
                    emit(r - 1, c, f2fma(bwy1, hcur[c], f2mul(bwy0, hprev[c])));
            }
#pragma unroll
            for (int c = 0; c < PC - 1; c++) hprev[c] = hcur[c];
        }
        return;
    }

    const float2 z = make_float2(0.f, 0.f);
    for (int r = 0; r < PC; r++) {
        int yy = by0 + r;
        bool yok = (unsigned)yy < (unsigned)H;
        float2 p[PC];
#pragma unroll
        for (int c = 0; c < PC; c++) {
            int xx = bx0 + c;
            bool ok = yok && ((unsigned)xx < (unsigned)W);
            p[c] = ok ? md[(yy * W + xx) * D2] : z;
        }
        float2 hcur[PC - 1];
#pragma unroll
        for (int c = 0; c < PC - 1; c++)
            hcur[c] = f2fma(bwx1, p[c + 1], f2mul(bwx0, p[c]));
        if (r > 0) {
#pragma unroll
            for (int c = 0; c < PC - 1; c++)
                emit(r - 1, c, f2fma(bwy1, hcur[c], f2mul(bwy0, hprev[c])));
        }
#pragma unroll
        for (int c = 0; c < PC - 1; c++) hprev[c] = hcur[c];
    }
}

// ---------------------------------------------------------------------------
// Gather kernel: 192 threads = 2 independent 96-thread query groups.
// Per-level loops; no smem; (192,4) bound; interior fast paths; fast GELU.
// ---------------------------------------------------------------------------
__global__ __launch_bounds__(DD, 4) void gather_kernel(
    const float* __restrict__ coords,
    const float* __restrict__ proj_l2_b, const float* __restrict__ proj_l4_b,
    const float* __restrict__ e_l1, const float* __restrict__ e_l2,
    const float* __restrict__ e_l3, const float* __restrict__ e_l4,
    const float* __restrict__ rpe,
    float* __restrict__ out_tokens)
{
    const int tid = threadIdx.x;
    const int q0 = blockIdx.x * QT;
    const int g = tid / D2;
    const int c = tid % D2;

    const float2* crd = (const float2*)coords;
    const float2* rp = (const float2*)rpe;
    const float2* pwt = (const float2*)g_phiW;

    // ---- Loop 1: l1 fixed (24) + learned (8) tokens ----
    {
        const float2 e1 = ((const float2*)e_l1)[c];
        const float2* lxy2 = (const float2*)g_lxy;
        const float2* phiLW2 = (const float2*)g_phiLW2;
        for (int qq = g; qq < QT; qq += 2) {
            const int qi = q0 + qq;
            const int b = qi >> 12;
            const float2 xy = __ldg(&crd[qi]);
            const float xc = xy.x * 0.25f, yc = xy.y * 0.25f;
            float2* tb = (float2*)out_tokens + (size_t)qi * 91 * D2 + c;
            const float2* m1b = (const float2*)g_m1 + (size_t)b * (H1 * W1) * D2 + c;

            patch_sample2<H1, W1, 2>(m1b, xc, yc,
                [&](int ty, int tx, float2 v) {
                    int idx = ty * 5 + tx;
                    if (idx == 12) return;
                    int t = (idx < 12) ? idx : idx - 1;
                    v = f2add(v, __ldg(&pwt[t * D2 + c]));
                    __stcs(&tb[t * D2], f2add(gelu2(v), e1));
                });

            for (int t = 0; t < 8; t++) {
                float2 off = __ldg(&lxy2[(size_t)qi * 8 + t]);
                float2 v = sample2<H1, W1>(m1b, xc + off.x, yc + off.y);
                float2 pw = __ldcs(&phiLW2[((size_t)qi * 8 + t) * D2 + c]);
                v = f2add(v, pw);
                __stcs(&tb[(24 + t) * D2], f2add(gelu2(v), e1));
            }
        }
    }

    // ---- Loop 2: l2 tokens (25) ----
    {
        const float2 b2e = f2add(((const float2*)proj_l2_b)[c], ((const float2*)e_l2)[c]);
        for (int qq = g; qq < QT; qq += 2) {
            const int qi = q0 + qq;
            const int b = qi >> 12;
            const float2 xy = __ldg(&crd[qi]);
            float2* tb = (float2*)out_tokens + (size_t)qi * 91 * D2 + c;
            const float2* m2b = (const float2*)g_m2 + (size_t)b * (H2 * W2) * D2 + c;
            patch_sample2<H2, W2, 2>(m2b, xy.x * 0.125f, xy.y * 0.125f,
                [&](int ty, int tx, float2 v) {
                    int t = ty * 5 + tx;
                    __stcs(&tb[(32 + t) * D2],
                           f2add(f2add(v, b2e), __ldg(&rp[t * D2 + c])));
                });
        }
    }

    // ---- Loop 3: l3 tokens (25) ----
    {
        const float2 e3 = ((const float2*)e_l3)[c];
        for (int qq = g; qq < QT; qq += 2) {
            const int qi = q0 + qq;
            const int b = qi >> 12;
            const float2 xy = __ldg(&crd[qi]);
            float2* tb = (float2*)out_tokens + (size_t)qi * 91 * D2 + c;
            const float2* m3b = (const float2*)g_m3 + (size_t)b * (H3 * W3) * D2 + c;
            patch_sample2<H3, W3, 2>(m3b, xy.x * 0.0625f, xy.y * 0.0625f,
                [&](int ty, int tx, float2 v) {
                    int t = ty * 5 + tx;
                    __stcs(&tb[(57 + t) * D2],
                           f2add(f2add(v, e3), __ldg(&rp[t * D2 + c])));
                });
        }
    }

    // ---- Loop 4: l4 tokens (9) ----
    {
        const float2 b4e = f2add(((const float2*)proj_l4_b)[c], ((const float2*)e_l4)[c]);
        for (int qq = g; qq < QT; qq += 2) {
            const int qi = q0 + qq;
            const int b = qi >> 12;
            const float2 xy = __ldg(&crd[qi]);
            float2* tb = (float2*)out_tokens + (size_t)qi * 91 * D2 + c;
            const float2* m4b = (const float2*)g_m4 + (size_t)b * (H4 * W4) * D2 + c;
            patch_sample2<H4, W4, 1>(m4b, xy.x * 0.03125f, xy.y * 0.03125f,
                [&](int ty, int tx, float2 v) {
                    int t = ty * 3 + tx;
                    int ridx = 6 + (t / 3) * 5 + (t % 3);
                    __stcs(&tb[(82 + t) * D2],
                           f2add(f2add(v, b4e), __ldg(&rp[ridx * D2 + c])));
                });
        }
    }
}

// ---------------------------------------------------------------------------
extern "C" void kernel_launch(void* const* d_in, const int* in_sizes, int n_in,
                              void* d_out, int out_size)
{
    const float* feat_l1   = (const float*)d_in[0];
    const float* feat_l2   = (const float*)d_in[1];
    const float* feat_l3   = (const float*)d_in[2];
    const float* feat_l4   = (const float*)d_in[3];
    const float* coords    = (const float*)d_in[4];
    const float* proj_l2_w = (const float*)d_in[5];
    const float* proj_l2_b = (const float*)d_in[6];
    const float* proj_l4_w = (const float*)d_in[7];
    const float* proj_l4_b = (const float*)d_in[8];
    const float* w_off_w   = (const float*)d_in[9];
    const float* w_off_b   = (const float*)d_in[10];
    const float* w_loc_w   = (const float*)d_in[11];
    const float* w_loc_b   = (const float*)d_in[12];
    const float* w_q_w     = (const float*)d_in[13];
    const float* w_q_b     = (const float*)d_in[14];
    const float* e_l1      = (const float*)d_in[15];
    const float* e_l2      = (const float*)d_in[16];
    const float* e_l3      = (const float*)d_in[17];
    const float* e_l4      = (const float*)d_in[18];
    const float* rpe       = (const float*)d_in[19];

    float* out = (float*)d_out;
    float* out_tokens = out;
    float* out_seed = out + (size_t)NQ * 91 * DD;

    proj_map_kernel<64, 1><<<dim3(H1 * W1 / 8, BB), DD>>>(feat_l1, w_loc_w, H1 * W1);
    proj_map_kernel<128, 2><<<dim3(H2 * W2 / 8, BB), DD>>>(feat_l2, proj_l2_w, H2 * W2);
    proj_map_kernel<384, 4><<<dim3(H4 * W4 / 8, BB), DD>>>(feat_l4, proj_l4_w, H4 * W4);
    l3_transpose_kernel<<<dim3(H3 * W3 / 32, BB, 6), 256>>>(feat_l3);
    init_tables_kernel<<<24, DD>>>(w_loc_w, w_loc_b);

    seed_off_kernel<<<NQ / QT, DD>>>(coords, w_off_w, w_off_b, w_loc_w, w_loc_b,
                                     w_q_w, w_q_b, out_seed);

    gather_kernel<<<NQ / QT, DD>>>(coords, proj_l2_b, proj_l4_b,
                                   e_l1, e_l2, e_l3, e_l4, rpe, out_tokens);
}